// round 3
// baseline (speedup 1.0000x reference)
#include <cuda_runtime.h>
#include <cuda_bf16.h>

// Problem constants
#define Bn 2
#define Pn 2048
#define Cn 128
#define Hh 8
#define Tn 128
#define Nn (Bn*Cn*Pn)   // 524288 elements per [B][C][P] buffer
#define BPn (Bn*Pn)     // 4096 tokens

// One big scratch buffer (device global; no allocations).
// Layout (floats):
//  [0]      xT      : x transposed [B][C][P]
//  [1N]     ln1T    : layernorm1(x) transposed
//  [2N]     q, [3N] k, [4N] v  : conv outputs (pre-BN for q,k)
//  [5N]     attn    : attention output + conv_atten, [B][P][C]
//  [6N]     h       : proj output [B][P][C]
//  [7N] a1, [8N] a2, [9N] a3   : msgfa intermediates [B][C][P]
//  [10N]    x2      : [B][P][C]
//  [11N]    ln2     : [B][P][C]
//  [12N]    bn      : 4*C (scale_q, shift_q, scale_k, shift_k)
//  [12N+4C] xm      : B*P
//  [12N+4C+BP] gate : B*P
__device__ float g_scratch[12*Nn + 4*Cn + 2*BPn];

// ---------------------------------------------------------------------------
// Kernel 1: LayerNorm over C + transpose to channel-major; also transpose raw x
// grid = B*P blocks, 128 threads (thread = channel)
// ---------------------------------------------------------------------------
__global__ void __launch_bounds__(128) k_ln1(const float* __restrict__ x,
                                             const float* __restrict__ g,
                                             const float* __restrict__ bta,
                                             float* __restrict__ xT,
                                             float* __restrict__ lnT) {
    int bp = blockIdx.x;
    int b = bp >> 11;           // P = 2048
    int p = bp & 2047;
    int c = threadIdx.x;
    float v = x[bp * Cn + c];

    __shared__ float sb[8];
    float s = v, ss = v * v;
    #pragma unroll
    for (int o = 16; o; o >>= 1) {
        s  += __shfl_xor_sync(0xffffffffu, s,  o);
        ss += __shfl_xor_sync(0xffffffffu, ss, o);
    }
    int lane = c & 31, w = c >> 5;
    if (lane == 0) { sb[w] = s; sb[4 + w] = ss; }
    __syncthreads();
    s  = sb[0] + sb[1] + sb[2] + sb[3];
    ss = sb[4] + sb[5] + sb[6] + sb[7];
    float mean = s * (1.0f / Cn);
    float var  = ss * (1.0f / Cn) - mean * mean;
    float rs   = rsqrtf(var + 1e-6f);
    float ln   = (v - mean) * rs * g[c] + bta[c];
    int o = (b * Cn + c) * Pn + p;
    xT[o] = v;
    lnT[o] = ln;
}

// ---------------------------------------------------------------------------
// Generic conv3d kernel, channel-major activations.
// K=3: pad 1 all sides. K=2: pad 1 front (causal). K=1: pointwise.
// grid = B*T blocks, 128 threads (thread = output channel).
// Optional residual add.
// ---------------------------------------------------------------------------
template<int K, bool RES>
__global__ void __launch_bounds__(128) k_conv(const float* __restrict__ in,
                                              const float* __restrict__ wgt,
                                              const float* __restrict__ res,
                                              float* __restrict__ out) {
    constexpr int K3  = K * K * K;
    constexpr int SL  = K * 16;          // floats per ci staged
    constexpr int OFF = (K >= 2) ? 1 : 0;
    __shared__ float s_in[Cn * SL];

    int b = blockIdx.x >> 7;             // T = 128
    int d = blockIdx.x & 127;
    int tid = threadIdx.x;

    // Stage input slices d-OFF .. d-OFF+K-1 for all 128 input channels
    float4* s4 = reinterpret_cast<float4*>(s_in);
    for (int i = tid; i < Cn * K * 4; i += 128) {
        int ci = i / (K * 4);
        int r  = i - ci * (K * 4);
        int sl = r >> 2;
        int v4 = r & 3;
        int dd = d + sl - OFF;
        float4 val = make_float4(0.f, 0.f, 0.f, 0.f);
        if (dd >= 0 && dd < Tn)
            val = *reinterpret_cast<const float4*>(in + (b * Cn + ci) * Pn + dd * 16 + v4 * 4);
        s4[i] = val;
    }
    __syncthreads();

    int co = tid;
    float acc[16];
    #pragma unroll
    for (int s = 0; s < 16; s++) acc[s] = 0.f;

    const float* wbase = wgt + (long)co * Cn * K3;

    #pragma unroll 1
    for (int ci = 0; ci < Cn; ci++) {
        // Broadcast-load this ci's staged slices into registers
        float rin[SL];
        {
            float4* r4 = reinterpret_cast<float4*>(rin);
            const float4* src4 = reinterpret_cast<const float4*>(s_in + ci * SL);
            #pragma unroll
            for (int i = 0; i < K * 4; i++) r4[i] = src4[i];
        }
        float wv[K3];
        const float* wp = wbase + ci * K3;
        #pragma unroll
        for (int i = 0; i < K3; i++) wv[i] = __ldg(wp + i);

        #pragma unroll
        for (int kd = 0; kd < K; kd++)
        #pragma unroll
        for (int kh = 0; kh < K; kh++)
        #pragma unroll
        for (int kw = 0; kw < K; kw++) {
            float w0 = wv[(kd * K + kh) * K + kw];
            #pragma unroll
            for (int h = 0; h < 4; h++) {
                int ih = h + kh - OFF;
                if (ih < 0 || ih > 3) continue;
                #pragma unroll
                for (int w = 0; w < 4; w++) {
                    int iw = w + kw - OFF;
                    if (iw < 0 || iw > 3) continue;
                    acc[h * 4 + w] = fmaf(w0, rin[kd * 16 + ih * 4 + iw], acc[h * 4 + w]);
                }
            }
        }
    }

    int ob = (b * Cn + co) * Pn + d * 16;
    #pragma unroll
    for (int s = 0; s < 16; s++) {
        float v = acc[s];
        if (RES) v += res[ob + s];
        out[ob + s] = v;
    }
}

// ---------------------------------------------------------------------------
// BatchNorm statistics for q and k (training-mode batch stats per channel),
// folded into scale/shift. grid = 2*C blocks (q then k), 256 threads.
// ---------------------------------------------------------------------------
__global__ void __launch_bounds__(256) k_bnstats(const float* __restrict__ q,
                                                 const float* __restrict__ k,
                                                 const float* __restrict__ qg,
                                                 const float* __restrict__ qb,
                                                 const float* __restrict__ kg,
                                                 const float* __restrict__ kb,
                                                 float* __restrict__ bn) {
    int which = blockIdx.x >> 7;
    int c = blockIdx.x & 127;
    const float* src = which ? k : q;

    float s = 0.f, ss = 0.f;
    for (int b = 0; b < Bn; b++) {
        const float* row = src + (b * Cn + c) * Pn;
        for (int p = threadIdx.x; p < Pn; p += 256) {
            float v = row[p];
            s += v; ss += v * v;
        }
    }
    __shared__ float sb[16];
    #pragma unroll
    for (int o = 16; o; o >>= 1) {
        s  += __shfl_xor_sync(0xffffffffu, s,  o);
        ss += __shfl_xor_sync(0xffffffffu, ss, o);
    }
    int lane = threadIdx.x & 31, w = threadIdx.x >> 5;
    if (lane == 0) { sb[w] = s; sb[8 + w] = ss; }
    __syncthreads();
    if (threadIdx.x == 0) {
        float S = 0.f, SS = 0.f;
        #pragma unroll
        for (int i = 0; i < 8; i++) { S += sb[i]; SS += sb[8 + i]; }
        const float invN = 1.0f / (Bn * Pn);
        float mean = S * invN;
        float var  = SS * invN - mean * mean;
        float rs   = rsqrtf(var + 1e-5f);
        float gam  = which ? kg[c] : qg[c];
        float bet  = which ? kb[c] : qb[c];
        float scale = rs * gam;
        float shift = bet - mean * scale;
        bn[which * 2 * Cn + c]      = scale;
        bn[which * 2 * Cn + Cn + c] = shift;
    }
}

// ---------------------------------------------------------------------------
// Attention: thread-per-query-row online softmax, head dim 16, no scale.
// grid = B*H*(P/128) = 256 blocks, 128 threads. BN applied on the fly.
// Writes attention output to attn[B][P][C].
// ---------------------------------------------------------------------------
__global__ void __launch_bounds__(128) k_attn(const float* __restrict__ q,
                                              const float* __restrict__ k,
                                              const float* __restrict__ v,
                                              const float* __restrict__ bn,
                                              float* __restrict__ attn) {
    __shared__ float sK[16 * 128];
    __shared__ float sV[16 * 128];

    int bi = blockIdx.x;
    int qt = bi & 15;
    int hh = (bi >> 4) & 7;
    int b  = bi >> 7;
    int tid = threadIdx.x;
    int qrow = qt * 128 + tid;

    const float* scq = bn;
    const float* shq = bn + Cn;
    const float* sck = bn + 2 * Cn;
    const float* shk = bn + 3 * Cn;

    float qv[16];
    #pragma unroll
    for (int c16 = 0; c16 < 16; c16++) {
        int c = hh * 16 + c16;
        qv[c16] = q[(b * Cn + c) * Pn + qrow] * scq[c] + shq[c];
    }

    float m = -1e30f, l = 0.f;
    float o[16];
    #pragma unroll
    for (int i = 0; i < 16; i++) o[i] = 0.f;

    for (int kt = 0; kt < 16; kt++) {
        __syncthreads();
        for (int i = tid; i < 16 * 128; i += 128) {
            int c16 = i >> 7;
            int j   = i & 127;
            int c   = hh * 16 + c16;
            int gi  = (b * Cn + c) * Pn + kt * 128 + j;
            sK[i] = k[gi] * sck[c] + shk[c];
            sV[i] = v[gi];
        }
        __syncthreads();

        for (int j = 0; j < 128; j += 4) {
            float s0 = 0.f, s1 = 0.f, s2 = 0.f, s3 = 0.f;
            #pragma unroll
            for (int c16 = 0; c16 < 16; c16++) {
                float4 kk = *reinterpret_cast<const float4*>(&sK[c16 * 128 + j]);
                float qq = qv[c16];
                s0 = fmaf(qq, kk.x, s0);
                s1 = fmaf(qq, kk.y, s1);
                s2 = fmaf(qq, kk.z, s2);
                s3 = fmaf(qq, kk.w, s3);
            }
            float mn = fmaxf(fmaxf(s0, s1), fmaxf(s2, s3));
            if (mn > m) {
                float al = __expf(m - mn);
                m = mn;
                l *= al;
                #pragma unroll
                for (int i = 0; i < 16; i++) o[i] *= al;
            }
            float p0 = __expf(s0 - m);
            float p1 = __expf(s1 - m);
            float p2 = __expf(s2 - m);
            float p3 = __expf(s3 - m);
            l += (p0 + p1) + (p2 + p3);
            #pragma unroll
            for (int c16 = 0; c16 < 16; c16++) {
                float4 vv = *reinterpret_cast<const float4*>(&sV[c16 * 128 + j]);
                o[c16] = fmaf(p0, vv.x, fmaf(p1, vv.y, fmaf(p2, vv.z, fmaf(p3, vv.w, o[c16]))));
            }
        }
    }
    float inv = 1.0f / l;
    int ob = (b * Pn + qrow) * Cn + hh * 16;
    #pragma unroll
    for (int c16 = 0; c16 < 16; c16++)
        attn[ob + c16] = o[c16] * inv;
}

// ---------------------------------------------------------------------------
// conv_atten: interleaved q/k/v head-channel mean, added into attn.
// out[b,p,hd,w2] += mean over r in {0,1,2} of X[j=r*16+w2],
//   X[j] picks source s=j%3 (0:qn,1:kn,2:v) channel hd*16 + j/3.
// ---------------------------------------------------------------------------
__global__ void __launch_bounds__(256) k_convatten(const float* __restrict__ q,
                                                   const float* __restrict__ k,
                                                   const float* __restrict__ v,
                                                   const float* __restrict__ bn,
                                                   float* __restrict__ attn) {
    int i = blockIdx.x * 256 + threadIdx.x;   // i < B*P*C
    int c  = i & 127;
    int bp = i >> 7;
    int b  = bp >> 11;
    int p  = bp & 2047;
    int hd = c >> 4;
    int w2 = c & 15;

    const float* scq = bn;
    const float* shq = bn + Cn;
    const float* sck = bn + 2 * Cn;
    const float* shk = bn + 3 * Cn;

    float acc = 0.f;
    #pragma unroll
    for (int r = 0; r < 3; r++) {
        int j  = r * 16 + w2;
        int wi = j / 3;
        int s  = j - wi * 3;
        int ch = hd * 16 + wi;
        int off = (b * Cn + ch) * Pn + p;
        float val;
        if (s == 0)      val = q[off] * scq[ch] + shq[ch];
        else if (s == 1) val = k[off] * sck[ch] + shk[ch];
        else             val = v[off];
        acc += val;
    }
    attn[i] += acc * (1.0f / 3.0f);
}

// ---------------------------------------------------------------------------
// proj: h = attn @ proj_w^T + proj_b.  grid = BP/16 blocks, 128 threads.
// ---------------------------------------------------------------------------
__global__ void __launch_bounds__(128) k_proj(const float* __restrict__ x,
                                              const float* __restrict__ wgt,
                                              const float* __restrict__ bias,
                                              float* __restrict__ out) {
    __shared__ float sx[16 * 128];
    int t0 = blockIdx.x * 16;
    int tid = threadIdx.x;
    for (int i = tid; i < 2048; i += 128)
        sx[i] = x[t0 * Cn + i];
    __syncthreads();

    float acc[16];
    #pragma unroll
    for (int t = 0; t < 16; t++) acc[t] = 0.f;

    #pragma unroll 4
    for (int ci = 0; ci < Cn; ci++) {
        float wv = __ldg(wgt + tid * Cn + ci);
        #pragma unroll
        for (int t = 0; t < 16; t++)
            acc[t] = fmaf(wv, sx[t * 128 + ci], acc[t]);
    }
    float bb = bias[tid];
    #pragma unroll
    for (int t = 0; t < 16; t++)
        out[(t0 + t) * Cn + tid] = acc[t] + bb;
}

// ---------------------------------------------------------------------------
// combine: x2 = msgfa_mean(a1,a2,a3) + h; then layernorm2(x2) and xm (channel
// mean of ln2). grid = B*P blocks, 128 threads.
// ---------------------------------------------------------------------------
__global__ void __launch_bounds__(128) k_combine(const float* __restrict__ a1,
                                                 const float* __restrict__ a2,
                                                 const float* __restrict__ a3,
                                                 const float* __restrict__ hbuf,
                                                 const float* __restrict__ g2,
                                                 const float* __restrict__ b2,
                                                 float* __restrict__ x2,
                                                 float* __restrict__ ln2,
                                                 float* __restrict__ xm) {
    int bp = blockIdx.x;
    int b = bp >> 11;
    int p = bp & 2047;
    int ci = threadIdx.x;

    float sacc = 0.f;
    #pragma unroll
    for (int kk = 0; kk < 3; kk++) {
        int j   = 3 * ci + kk;
        int src = j >> 7;
        int ch  = j & 127;
        const float* a = (src == 0) ? a1 : (src == 1) ? a2 : a3;
        sacc += a[(b * Cn + ch) * Pn + p];
    }
    float x2v = sacc * (1.0f / 3.0f) + hbuf[bp * Cn + ci];

    __shared__ float sb[8];
    float s = x2v, ss = x2v * x2v;
    #pragma unroll
    for (int o = 16; o; o >>= 1) {
        s  += __shfl_xor_sync(0xffffffffu, s,  o);
        ss += __shfl_xor_sync(0xffffffffu, ss, o);
    }
    int lane = ci & 31, w = ci >> 5;
    if (lane == 0) { sb[w] = s; sb[4 + w] = ss; }
    __syncthreads();
    s  = sb[0] + sb[1] + sb[2] + sb[3];
    ss = sb[4] + sb[5] + sb[6] + sb[7];
    float mean = s * (1.0f / Cn);
    float var  = ss * (1.0f / Cn) - mean * mean;
    float rs   = rsqrtf(var + 1e-6f);
    float ln   = (x2v - mean) * rs * g2[ci] + b2[ci];

    x2[bp * Cn + ci]  = x2v;
    ln2[bp * Cn + ci] = ln;

    // xm = mean over channels of ln2
    __syncthreads();
    float t = ln;
    #pragma unroll
    for (int o = 16; o; o >>= 1)
        t += __shfl_xor_sync(0xffffffffu, t, o);
    if (lane == 0) sb[w] = t;
    __syncthreads();
    if (ci == 0)
        xm[bp] = (sb[0] + sb[1] + sb[2] + sb[3]) * (1.0f / Cn);
}

// ---------------------------------------------------------------------------
// gate: g = st1*xm + conv2_causal(xm) + conv3_pad1(xm); gate = sigmoid(g)
// ---------------------------------------------------------------------------
__global__ void __launch_bounds__(256) k_gate(const float* __restrict__ xm,
                                              const float* __restrict__ st1,
                                              const float* __restrict__ st2,
                                              const float* __restrict__ st3,
                                              float* __restrict__ gate) {
    int i = blockIdx.x * 256 + threadIdx.x;
    if (i >= Bn * Pn) return;
    int b = i >> 11;
    int p = i & 2047;
    int t  = p >> 4;
    int h4 = (p >> 2) & 3;
    int w4 = p & 3;
    const float* X = xm + b * Pn;

    float gsum = st1[0] * X[p];
    #pragma unroll
    for (int kd = 0; kd < 2; kd++)
    #pragma unroll
    for (int kh = 0; kh < 2; kh++)
    #pragma unroll
    for (int kw = 0; kw < 2; kw++) {
        int tt = t + kd - 1, hh = h4 + kh - 1, ww = w4 + kw - 1;
        float v = (tt >= 0 && hh >= 0 && ww >= 0)
                  ? X[tt * 16 + hh * 4 + ww] : 0.f;
        gsum = fmaf(st2[kd * 4 + kh * 2 + kw], v, gsum);
    }
    #pragma unroll
    for (int kd = 0; kd < 3; kd++)
    #pragma unroll
    for (int kh = 0; kh < 3; kh++)
    #pragma unroll
    for (int kw = 0; kw < 3; kw++) {
        int tt = t + kd - 1, hh = h4 + kh - 1, ww = w4 + kw - 1;
        float v = (tt >= 0 && tt < Tn && hh >= 0 && hh < 4 && ww >= 0 && ww < 4)
                  ? X[tt * 16 + hh * 4 + ww] : 0.f;
        gsum = fmaf(st3[(kd * 3 + kh) * 3 + kw], v, gsum);
    }
    gate[i] = 1.0f / (1.0f + __expf(-gsum));
}

// ---------------------------------------------------------------------------
// final: out = x2 + ln2 * gate (gate broadcast over channels)
// ---------------------------------------------------------------------------
__global__ void __launch_bounds__(256) k_final(const float* __restrict__ x2,
                                               const float* __restrict__ ln2,
                                               const float* __restrict__ gate,
                                               float* __restrict__ out) {
    int i = blockIdx.x * 256 + threadIdx.x;
    if (i >= Bn * Pn * Cn) return;
    out[i] = x2[i] + ln2[i] * gate[i >> 7];
}

// ---------------------------------------------------------------------------
// Launch
// ---------------------------------------------------------------------------
extern "C" void kernel_launch(void* const* d_in, const int* in_sizes, int n_in,
                              void* d_out, int out_size) {
    const float* x      = (const float*)d_in[0];
    const float* n1g    = (const float*)d_in[1];
    const float* n1b    = (const float*)d_in[2];
    const float* q_w    = (const float*)d_in[3];
    const float* q_bn_g = (const float*)d_in[4];
    const float* q_bn_b = (const float*)d_in[5];
    const float* k_w    = (const float*)d_in[6];
    const float* k_bn_g = (const float*)d_in[7];
    const float* k_bn_b = (const float*)d_in[8];
    const float* v_w    = (const float*)d_in[9];
    const float* proj_w = (const float*)d_in[10];
    const float* proj_b = (const float*)d_in[11];
    const float* r1_w   = (const float*)d_in[12];
    const float* r2_w   = (const float*)d_in[13];
    const float* r3_w   = (const float*)d_in[14];
    const float* n2g    = (const float*)d_in[15];
    const float* n2b    = (const float*)d_in[16];
    const float* st1    = (const float*)d_in[17];
    const float* st2    = (const float*)d_in[18];
    const float* st3    = (const float*)d_in[19];
    // d_in[20] = num_heads (int) — hardcoded to 8

    float* base = nullptr;
    cudaGetSymbolAddress((void**)&base, g_scratch);

    float* XT   = base;
    float* LN1  = base + 1 * Nn;
    float* Q    = base + 2 * Nn;
    float* Kb   = base + 3 * Nn;
    float* V    = base + 4 * Nn;
    float* ATT  = base + 5 * Nn;
    float* Hb   = base + 6 * Nn;
    float* A1   = base + 7 * Nn;
    float* A2   = base + 8 * Nn;
    float* A3   = base + 9 * Nn;
    float* X2   = base + 10 * Nn;
    float* LN2  = base + 11 * Nn;
    float* BN   = base + 12 * Nn;
    float* XM   = BN + 4 * Cn;
    float* GATE = XM + BPn;

    float* out = (float*)d_out;

    // 1. layernorm1 + transpose (also raw x transpose for msgfa)
    k_ln1<<<BPn, 128>>>(x, n1g, n1b, XT, LN1);

    // 2-4. q/k/v convs on ln1
    k_conv<3, false><<<Bn * Tn, 128>>>(LN1, q_w, nullptr, Q);
    k_conv<2, false><<<Bn * Tn, 128>>>(LN1, k_w, nullptr, Kb);
    k_conv<1, false><<<Bn * Tn, 128>>>(LN1, v_w, nullptr, V);

    // 5. BN stats (fold into scale/shift)
    k_bnstats<<<2 * Cn, 256>>>(Q, Kb, q_bn_g, q_bn_b, k_bn_g, k_bn_b, BN);

    // 6. attention
    k_attn<<<Bn * Hh * (Pn / 128), 128>>>(Q, Kb, V, BN, ATT);

    // 7. conv_atten add
    k_convatten<<<(Bn * Pn * Cn) / 256, 256>>>(Q, Kb, V, BN, ATT);

    // 8. proj
    k_proj<<<BPn / 16, 128>>>(ATT, proj_w, proj_b, Hb);

    // 9-11. msgfa convs with residuals (on raw x)
    k_conv<3, true><<<Bn * Tn, 128>>>(XT, r1_w, XT, A1);
    k_conv<2, true><<<Bn * Tn, 128>>>(A1, r2_w, A1, A2);
    k_conv<1, true><<<Bn * Tn, 128>>>(A2, r3_w, A2, A3);

    // 12. combine: x2 = s + h, layernorm2, xm
    k_combine<<<BPn, 128>>>(A1, A2, A3, Hb, n2g, n2b, X2, LN2, XM);

    // 13. gate
    k_gate<<<(BPn + 255) / 256, 256>>>(XM, st1, st2, st3, GATE);

    // 14. final
    k_final<<<(Bn * Pn * Cn + 255) / 256, 256>>>(X2, LN2, GATE, out);
}

// round 8
// speedup vs baseline: 3.7002x; 3.7002x over previous
#include <cuda_runtime.h>
#include <cuda_bf16.h>

// Problem constants
#define Bn 2
#define Pn 2048
#define Cn 128
#define Hh 8
#define Tn 128
#define Nn (Bn*Cn*Pn)   // 524288 elements per [B][C][P] buffer
#define BPn (Bn*Pn)     // 4096 tokens

// Transposed-weight segment sizes / offsets (within WT region)
#define S3 442368   // 128*128*27
#define S2 131072   // 128*128*8
#define S1 16384    // 128*128
#define WT_Q  0
#define WT_K  (S3)
#define WT_V  (S3+S2)
#define WT_R1 (S3+S2+S1)
#define WT_R2 (2*S3+S2+S1)
#define WT_R3 (2*S3+2*S2+S1)
#define WT_P  (2*S3+2*S2+2*S1)
#define WT_TOTAL (2*S3+2*S2+3*S1)   // 1196032

// Attention partials: 4 splits * 4096 rows * 8 heads * 18 floats
#define PART_TOTAL (4*4096*8*18)    // 2359296

// Scratch layout (floats):
//  [0]  XT, [1N] LN1, [2N] Q, [3N] K, [4N] V   (channel-major [B][C][P])
//  [5N] ATT, [6N] Hb                            ([B][P][C])
//  [7N] A1, [8N] A2, [9N] A3                    (channel-major)
//  [10N] X2, [11N] LN2                          ([B][P][C])
//  [12N] BN(512), then XM(4096), GATE(4096)
//  then WT (transposed weights), then PART (attention partials)
__device__ float g_scratch[12*Nn + 512 + 2*BPn + WT_TOTAL + PART_TOTAL];

// ---------------------------------------------------------------------------
// Weight transpose: w[co][ci][tap] -> wT[(ci*K3+tap)*128 + co]; proj too.
// ---------------------------------------------------------------------------
__global__ void __launch_bounds__(256) k_wtrans(const float* __restrict__ qw,
                                                const float* __restrict__ kw,
                                                const float* __restrict__ vw,
                                                const float* __restrict__ r1,
                                                const float* __restrict__ r2,
                                                const float* __restrict__ r3,
                                                const float* __restrict__ pw,
                                                float* __restrict__ wt) {
    int i = blockIdx.x * 256 + threadIdx.x;
    if (i >= WT_TOTAL) return;
    const float* src; int K3; int base;
    if      (i < WT_K)  { src = qw; K3 = 27; base = WT_Q;  }
    else if (i < WT_V)  { src = kw; K3 = 8;  base = WT_K;  }
    else if (i < WT_R1) { src = vw; K3 = 1;  base = WT_V;  }
    else if (i < WT_R2) { src = r1; K3 = 27; base = WT_R1; }
    else if (i < WT_R3) { src = r2; K3 = 8;  base = WT_R2; }
    else if (i < WT_P)  { src = r3; K3 = 1;  base = WT_R3; }
    else {
        int e = i - WT_P; int co = e >> 7, ci = e & 127;
        wt[WT_P + ci * 128 + co] = pw[e];
        return;
    }
    int e  = i - base;
    int co = e / (128 * K3);
    int r  = e - co * 128 * K3;
    int ci = r / K3;
    int t  = r - ci * K3;
    wt[base + (ci * K3 + t) * 128 + co] = src[e];
}

// ---------------------------------------------------------------------------
// LayerNorm over C + transpose to channel-major; also transpose raw x
// ---------------------------------------------------------------------------
__global__ void __launch_bounds__(128) k_ln1(const float* __restrict__ x,
                                             const float* __restrict__ g,
                                             const float* __restrict__ bta,
                                             float* __restrict__ xT,
                                             float* __restrict__ lnT) {
    int bp = blockIdx.x;
    int b = bp >> 11;
    int p = bp & 2047;
    int c = threadIdx.x;
    float v = x[bp * Cn + c];

    __shared__ float sb[8];
    float s = v, ss = v * v;
    #pragma unroll
    for (int o = 16; o; o >>= 1) {
        s  += __shfl_xor_sync(0xffffffffu, s,  o);
        ss += __shfl_xor_sync(0xffffffffu, ss, o);
    }
    int lane = c & 31, w = c >> 5;
    if (lane == 0) { sb[w] = s; sb[4 + w] = ss; }
    __syncthreads();
    s  = sb[0] + sb[1] + sb[2] + sb[3];
    ss = sb[4] + sb[5] + sb[6] + sb[7];
    float mean = s * (1.0f / Cn);
    float var  = ss * (1.0f / Cn) - mean * mean;
    float rs   = rsqrtf(var + 1e-6f);
    float ln   = (v - mean) * rs * g[c] + bta[c];
    int o = (b * Cn + c) * Pn + p;
    xT[o] = v;
    lnT[o] = ln;
}

// ---------------------------------------------------------------------------
// Conv3d v2: grid = B*T*2 (co-halves), block 256 = 64 co x 4 ci-groups.
// Weights from transposed layout (coalesced). Smem reduction across groups.
// ---------------------------------------------------------------------------
template<int K, bool RES>
__global__ void __launch_bounds__(256) k_conv2(const float* __restrict__ in,
                                               const float* __restrict__ wT,
                                               const float* __restrict__ res,
                                               float* __restrict__ out) {
    constexpr int K3  = K * K * K;
    constexpr int SL  = K * 16;
    constexpr int OFF = (K >= 2) ? 1 : 0;
    __shared__ float s_in[Cn * SL];
    __shared__ float s_red[3 * 64 * 16];

    int bid  = blockIdx.x;
    int half = bid & 1;
    int bd   = bid >> 1;
    int b = bd >> 7, d = bd & 127;
    int tid = threadIdx.x;
    int col = tid & 63, g = tid >> 6;
    int co  = half * 64 + col;

    // Stage input slices d-OFF .. d-OFF+K-1 for all 128 input channels
    float4* s4 = reinterpret_cast<float4*>(s_in);
    for (int i = tid; i < Cn * K * 4; i += 256) {
        int ci = i / (K * 4);
        int r  = i - ci * (K * 4);
        int sl = r >> 2;
        int v4 = r & 3;
        int dd = d + sl - OFF;
        float4 val = make_float4(0.f, 0.f, 0.f, 0.f);
        if (dd >= 0 && dd < Tn)
            val = *reinterpret_cast<const float4*>(in + (b * Cn + ci) * Pn + dd * 16 + v4 * 4);
        s4[i] = val;
    }
    __syncthreads();

    float acc[16];
    #pragma unroll
    for (int s = 0; s < 16; s++) acc[s] = 0.f;

    int ci0 = g * 32;
    #pragma unroll 1
    for (int cc = 0; cc < 32; cc++) {
        int ci = ci0 + cc;
        float rin[SL];
        {
            float4* r4 = reinterpret_cast<float4*>(rin);
            const float4* src4 = reinterpret_cast<const float4*>(s_in + ci * SL);
            #pragma unroll
            for (int i = 0; i < K * 4; i++) r4[i] = src4[i];
        }
        float wv[K3];
        const float* wp = wT + (ci * K3) * 128 + co;
        #pragma unroll
        for (int i = 0; i < K3; i++) wv[i] = __ldg(wp + i * 128);

        #pragma unroll
        for (int kd = 0; kd < K; kd++)
        #pragma unroll
        for (int kh = 0; kh < K; kh++)
        #pragma unroll
        for (int kw = 0; kw < K; kw++) {
            float w0 = wv[(kd * K + kh) * K + kw];
            #pragma unroll
            for (int h = 0; h < 4; h++) {
                int ih = h + kh - OFF;
                if (ih < 0 || ih > 3) continue;
                #pragma unroll
                for (int w = 0; w < 4; w++) {
                    int iw = w + kw - OFF;
                    if (iw < 0 || iw > 3) continue;
                    acc[h * 4 + w] = fmaf(w0, rin[kd * 16 + ih * 4 + iw], acc[h * 4 + w]);
                }
            }
        }
    }

    // Cross-group reduction: groups 1..3 dump partials, group 0 sums + stores.
    if (g) {
        float* dst = s_red + (g - 1) * 1024;
        #pragma unroll
        for (int s = 0; s < 16; s++) dst[s * 64 + col] = acc[s];
    }
    __syncthreads();
    if (g == 0) {
        #pragma unroll
        for (int s = 0; s < 16; s++)
            acc[s] += s_red[s * 64 + col] + s_red[1024 + s * 64 + col] + s_red[2048 + s * 64 + col];
        int ob = (b * Cn + co) * Pn + d * 16;
        if (RES) {
            const float4* rp = reinterpret_cast<const float4*>(res + ob);
            #pragma unroll
            for (int s = 0; s < 4; s++) {
                float4 rv = rp[s];
                acc[4*s+0] += rv.x; acc[4*s+1] += rv.y;
                acc[4*s+2] += rv.z; acc[4*s+3] += rv.w;
            }
        }
        float4* op = reinterpret_cast<float4*>(out + ob);
        #pragma unroll
        for (int s = 0; s < 4; s++)
            op[s] = make_float4(acc[4*s], acc[4*s+1], acc[4*s+2], acc[4*s+3]);
    }
}

// ---------------------------------------------------------------------------
// BatchNorm statistics for q and k, folded into scale/shift.
// ---------------------------------------------------------------------------
__global__ void __launch_bounds__(256) k_bnstats(const float* __restrict__ q,
                                                 const float* __restrict__ k,
                                                 const float* __restrict__ qg,
                                                 const float* __restrict__ qb,
                                                 const float* __restrict__ kg,
                                                 const float* __restrict__ kb,
                                                 float* __restrict__ bn) {
    int which = blockIdx.x >> 7;
    int c = blockIdx.x & 127;
    const float* src = which ? k : q;

    float s = 0.f, ss = 0.f;
    for (int b = 0; b < Bn; b++) {
        const float* row = src + (b * Cn + c) * Pn;
        for (int p = threadIdx.x; p < Pn; p += 256) {
            float v = row[p];
            s += v; ss += v * v;
        }
    }
    __shared__ float sb[16];
    #pragma unroll
    for (int o = 16; o; o >>= 1) {
        s  += __shfl_xor_sync(0xffffffffu, s,  o);
        ss += __shfl_xor_sync(0xffffffffu, ss, o);
    }
    int lane = threadIdx.x & 31, w = threadIdx.x >> 5;
    if (lane == 0) { sb[w] = s; sb[8 + w] = ss; }
    __syncthreads();
    if (threadIdx.x == 0) {
        float S = 0.f, SS = 0.f;
        #pragma unroll
        for (int i = 0; i < 8; i++) { S += sb[i]; SS += sb[8 + i]; }
        const float invN = 1.0f / (Bn * Pn);
        float mean = S * invN;
        float var  = SS * invN - mean * mean;
        float rs   = rsqrtf(var + 1e-5f);
        float gam  = which ? kg[c] : qg[c];
        float bet  = which ? kb[c] : qb[c];
        float scale = rs * gam;
        float shift = bet - mean * scale;
        bn[which * 2 * Cn + c]      = scale;
        bn[which * 2 * Cn + Cn + c] = shift;
    }
}

// ---------------------------------------------------------------------------
// Attention split kernel: 4-way key split, online softmax per split,
// writes partial (o[16], m, l) per (split, row, head).
// grid = 4 * B * H * 16 = 1024 blocks, 128 threads.
// ---------------------------------------------------------------------------
__global__ void __launch_bounds__(128) k_attn2(const float* __restrict__ q,
                                               const float* __restrict__ k,
                                               const float* __restrict__ v,
                                               const float* __restrict__ bn,
                                               float* __restrict__ part) {
    __shared__ float sK[16 * 128];
    __shared__ float sV[16 * 128];

    int bi = blockIdx.x;
    int qt = bi & 15;
    int hh = (bi >> 4) & 7;
    int b  = (bi >> 7) & 1;
    int split = bi >> 8;
    int tid = threadIdx.x;
    int qrow = qt * 128 + tid;

    const float* scq = bn;
    const float* shq = bn + Cn;
    const float* sck = bn + 2 * Cn;
    const float* shk = bn + 3 * Cn;

    float qv[16];
    #pragma unroll
    for (int c16 = 0; c16 < 16; c16++) {
        int c = hh * 16 + c16;
        qv[c16] = q[(b * Cn + c) * Pn + qrow] * scq[c] + shq[c];
    }

    float m = -1e30f, l = 0.f;
    float o[16];
    #pragma unroll
    for (int i = 0; i < 16; i++) o[i] = 0.f;

    for (int kt = split * 4; kt < split * 4 + 4; kt++) {
        __syncthreads();
        for (int i = tid; i < 16 * 128; i += 128) {
            int c16 = i >> 7;
            int j   = i & 127;
            int c   = hh * 16 + c16;
            int gi  = (b * Cn + c) * Pn + kt * 128 + j;
            sK[i] = k[gi] * sck[c] + shk[c];
            sV[i] = v[gi];
        }
        __syncthreads();

        for (int j = 0; j < 128; j += 4) {
            float s0 = 0.f, s1 = 0.f, s2 = 0.f, s3 = 0.f;
            #pragma unroll
            for (int c16 = 0; c16 < 16; c16++) {
                float4 kk = *reinterpret_cast<const float4*>(&sK[c16 * 128 + j]);
                float qq = qv[c16];
                s0 = fmaf(qq, kk.x, s0);
                s1 = fmaf(qq, kk.y, s1);
                s2 = fmaf(qq, kk.z, s2);
                s3 = fmaf(qq, kk.w, s3);
            }
            float mn = fmaxf(fmaxf(s0, s1), fmaxf(s2, s3));
            if (mn > m) {
                float al = __expf(m - mn);
                m = mn;
                l *= al;
                #pragma unroll
                for (int i = 0; i < 16; i++) o[i] *= al;
            }
            float p0 = __expf(s0 - m);
            float p1 = __expf(s1 - m);
            float p2 = __expf(s2 - m);
            float p3 = __expf(s3 - m);
            l += (p0 + p1) + (p2 + p3);
            #pragma unroll
            for (int c16 = 0; c16 < 16; c16++) {
                float4 vv = *reinterpret_cast<const float4*>(&sV[c16 * 128 + j]);
                o[c16] = fmaf(p0, vv.x, fmaf(p1, vv.y, fmaf(p2, vv.z, fmaf(p3, vv.w, o[c16]))));
            }
        }
    }

    int row = b * 2048 + qrow;
    float* pp = part + ((split * 4096 + row) * 8 + hh) * 18;
    #pragma unroll
    for (int c16 = 0; c16 < 16; c16++) pp[c16] = o[c16];
    pp[16] = m;
    pp[17] = l;
}

// ---------------------------------------------------------------------------
// Merge split-K partials + conv_atten add, writes ATT [B][P][C].
// grid = B*P*C/256 = 2048 blocks.
// ---------------------------------------------------------------------------
__global__ void __launch_bounds__(256) k_merge(const float* __restrict__ part,
                                               const float* __restrict__ q,
                                               const float* __restrict__ k,
                                               const float* __restrict__ v,
                                               const float* __restrict__ bn,
                                               float* __restrict__ att) {
    int i = blockIdx.x * 256 + threadIdx.x;   // i < B*P*C
    int c   = i & 127;
    int bp  = i >> 7;
    int b   = bp >> 11;
    int p   = bp & 2047;
    int hd  = c >> 4;
    int c16 = c & 15;

    float ms[4], ls[4], os[4];
    float M = -1e30f;
    #pragma unroll
    for (int s = 0; s < 4; s++) {
        const float* pp = part + ((s * 4096 + bp) * 8 + hd) * 18;
        os[s] = pp[c16]; ms[s] = pp[16]; ls[s] = pp[17];
        M = fmaxf(M, ms[s]);
    }
    float L = 0.f, O = 0.f;
    #pragma unroll
    for (int s = 0; s < 4; s++) {
        float wgt = __expf(ms[s] - M);
        L += ls[s] * wgt;
        O += os[s] * wgt;
    }
    float attv = O / L;

    // conv_atten: interleaved q/k/v head-channel mean
    const float* scq = bn;
    const float* shq = bn + Cn;
    const float* sck = bn + 2 * Cn;
    const float* shk = bn + 3 * Cn;
    int w2 = c16;
    float acc = 0.f;
    #pragma unroll
    for (int r = 0; r < 3; r++) {
        int j  = r * 16 + w2;
        int wi = j / 3;
        int s  = j - wi * 3;
        int ch = hd * 16 + wi;
        int off = (b * Cn + ch) * Pn + p;
        float val;
        if (s == 0)      val = q[off] * scq[ch] + shq[ch];
        else if (s == 1) val = k[off] * sck[ch] + shk[ch];
        else             val = v[off];
        acc += val;
    }
    att[i] = attv + acc * (1.0f / 3.0f);
}

// ---------------------------------------------------------------------------
// proj: h = attn @ proj_w^T + proj_b (transposed weight, 8-row tiles)
// grid = BP/8 = 512 blocks, 128 threads.
// ---------------------------------------------------------------------------
__global__ void __launch_bounds__(128) k_proj(const float* __restrict__ x,
                                              const float* __restrict__ wT,
                                              const float* __restrict__ bias,
                                              float* __restrict__ out) {
    __shared__ float sx[8 * 128];
    int t0 = blockIdx.x * 8;
    int tid = threadIdx.x;
    for (int i = tid; i < 1024; i += 128)
        sx[i] = x[t0 * Cn + i];
    __syncthreads();

    float acc[8];
    #pragma unroll
    for (int t = 0; t < 8; t++) acc[t] = 0.f;

    #pragma unroll 4
    for (int ci = 0; ci < Cn; ci++) {
        float wv = __ldg(wT + ci * 128 + tid);
        #pragma unroll
        for (int t = 0; t < 8; t++)
            acc[t] = fmaf(wv, sx[t * 128 + ci], acc[t]);
    }
    float bb = bias[tid];
    #pragma unroll
    for (int t = 0; t < 8; t++)
        out[(t0 + t) * Cn + tid] = acc[t] + bb;
}

// ---------------------------------------------------------------------------
// combine: x2 = msgfa_mean(a1,a2,a3) + h; layernorm2(x2); xm = mean_c(ln2)
// ---------------------------------------------------------------------------
__global__ void __launch_bounds__(128) k_combine(const float* __restrict__ a1,
                                                 const float* __restrict__ a2,
                                                 const float* __restrict__ a3,
                                                 const float* __restrict__ hbuf,
                                                 const float* __restrict__ g2,
                                                 const float* __restrict__ b2,
                                                 float* __restrict__ x2,
                                                 float* __restrict__ ln2,
                                                 float* __restrict__ xm) {
    int bp = blockIdx.x;
    int b = bp >> 11;
    int p = bp & 2047;
    int ci = threadIdx.x;

    float sacc = 0.f;
    #pragma unroll
    for (int kk = 0; kk < 3; kk++) {
        int j   = 3 * ci + kk;
        int src = j >> 7;
        int ch  = j & 127;
        const float* a = (src == 0) ? a1 : (src == 1) ? a2 : a3;
        sacc += a[(b * Cn + ch) * Pn + p];
    }
    float x2v = sacc * (1.0f / 3.0f) + hbuf[bp * Cn + ci];

    __shared__ float sb[8];
    float s = x2v, ss = x2v * x2v;
    #pragma unroll
    for (int o = 16; o; o >>= 1) {
        s  += __shfl_xor_sync(0xffffffffu, s,  o);
        ss += __shfl_xor_sync(0xffffffffu, ss, o);
    }
    int lane = ci & 31, w = ci >> 5;
    if (lane == 0) { sb[w] = s; sb[4 + w] = ss; }
    __syncthreads();
    s  = sb[0] + sb[1] + sb[2] + sb[3];
    ss = sb[4] + sb[5] + sb[6] + sb[7];
    float mean = s * (1.0f / Cn);
    float var  = ss * (1.0f / Cn) - mean * mean;
    float rs   = rsqrtf(var + 1e-6f);
    float ln   = (x2v - mean) * rs * g2[ci] + b2[ci];

    x2[bp * Cn + ci]  = x2v;
    ln2[bp * Cn + ci] = ln;

    __syncthreads();
    float t = ln;
    #pragma unroll
    for (int o = 16; o; o >>= 1)
        t += __shfl_xor_sync(0xffffffffu, t, o);
    if (lane == 0) sb[w] = t;
    __syncthreads();
    if (ci == 0)
        xm[bp] = (sb[0] + sb[1] + sb[2] + sb[3]) * (1.0f / Cn);
}

// ---------------------------------------------------------------------------
// gate: g = st1*xm + conv2_causal(xm) + conv3_pad1(xm); gate = sigmoid(g)
// ---------------------------------------------------------------------------
__global__ void __launch_bounds__(256) k_gate(const float* __restrict__ xm,
                                              const float* __restrict__ st1,
                                              const float* __restrict__ st2,
                                              const float* __restrict__ st3,
                                              float* __restrict__ gate) {
    int i = blockIdx.x * 256 + threadIdx.x;
    if (i >= Bn * Pn) return;
    int b = i >> 11;
    int p = i & 2047;
    int t  = p >> 4;
    int h4 = (p >> 2) & 3;
    int w4 = p & 3;
    const float* X = xm + b * Pn;

    float gsum = st1[0] * X[p];
    #pragma unroll
    for (int kd = 0; kd < 2; kd++)
    #pragma unroll
    for (int kh = 0; kh < 2; kh++)
    #pragma unroll
    for (int kw = 0; kw < 2; kw++) {
        int tt = t + kd - 1, hh = h4 + kh - 1, ww = w4 + kw - 1;
        float v = (tt >= 0 && hh >= 0 && ww >= 0)
                  ? X[tt * 16 + hh * 4 + ww] : 0.f;
        gsum = fmaf(st2[kd * 4 + kh * 2 + kw], v, gsum);
    }
    #pragma unroll
    for (int kd = 0; kd < 3; kd++)
    #pragma unroll
    for (int kh = 0; kh < 3; kh++)
    #pragma unroll
    for (int kw = 0; kw < 3; kw++) {
        int tt = t + kd - 1, hh = h4 + kh - 1, ww = w4 + kw - 1;
        float v = (tt >= 0 && tt < Tn && hh >= 0 && hh < 4 && ww >= 0 && ww < 4)
                  ? X[tt * 16 + hh * 4 + ww] : 0.f;
        gsum = fmaf(st3[(kd * 3 + kh) * 3 + kw], v, gsum);
    }
    gate[i] = 1.0f / (1.0f + __expf(-gsum));
}

// ---------------------------------------------------------------------------
// final: out = x2 + ln2 * gate (gate broadcast over channels)
// ---------------------------------------------------------------------------
__global__ void __launch_bounds__(256) k_final(const float* __restrict__ x2,
                                               const float* __restrict__ ln2,
                                               const float* __restrict__ gate,
                                               float* __restrict__ out) {
    int i = blockIdx.x * 256 + threadIdx.x;
    if (i >= Bn * Pn * Cn) return;
    out[i] = x2[i] + ln2[i] * gate[i >> 7];
}

// ---------------------------------------------------------------------------
// Launch
// ---------------------------------------------------------------------------
extern "C" void kernel_launch(void* const* d_in, const int* in_sizes, int n_in,
                              void* d_out, int out_size) {
    const float* x      = (const float*)d_in[0];
    const float* n1g    = (const float*)d_in[1];
    const float* n1b    = (const float*)d_in[2];
    const float* q_w    = (const float*)d_in[3];
    const float* q_bn_g = (const float*)d_in[4];
    const float* q_bn_b = (const float*)d_in[5];
    const float* k_w    = (const float*)d_in[6];
    const float* k_bn_g = (const float*)d_in[7];
    const float* k_bn_b = (const float*)d_in[8];
    const float* v_w    = (const float*)d_in[9];
    const float* proj_w = (const float*)d_in[10];
    const float* proj_b = (const float*)d_in[11];
    const float* r1_w   = (const float*)d_in[12];
    const float* r2_w   = (const float*)d_in[13];
    const float* r3_w   = (const float*)d_in[14];
    const float* n2g    = (const float*)d_in[15];
    const float* n2b    = (const float*)d_in[16];
    const float* st1    = (const float*)d_in[17];
    const float* st2    = (const float*)d_in[18];
    const float* st3    = (const float*)d_in[19];
    // d_in[20] = num_heads (int) — hardcoded to 8

    float* base = nullptr;
    cudaGetSymbolAddress((void**)&base, g_scratch);

    float* XT   = base;
    float* LN1  = base + 1 * Nn;
    float* Q    = base + 2 * Nn;
    float* Kb   = base + 3 * Nn;
    float* V    = base + 4 * Nn;
    float* ATT  = base + 5 * Nn;
    float* Hb   = base + 6 * Nn;
    float* A1   = base + 7 * Nn;
    float* A2   = base + 8 * Nn;
    float* A3   = base + 9 * Nn;
    float* X2   = base + 10 * Nn;
    float* LN2  = base + 11 * Nn;
    float* BN   = base + 12 * Nn;
    float* XM   = BN + 512;
    float* GATE = XM + BPn;
    float* WT   = GATE + BPn;
    float* PART = WT + WT_TOTAL;

    float* out = (float*)d_out;

    // 0. transpose all weights (coalesced layout)
    k_wtrans<<<(WT_TOTAL + 255) / 256, 256>>>(q_w, k_w, v_w, r1_w, r2_w, r3_w, proj_w, WT);

    // 1. layernorm1 + transpose (also raw x transpose for msgfa)
    k_ln1<<<BPn, 128>>>(x, n1g, n1b, XT, LN1);

    // 2-4. q/k/v convs on ln1
    k_conv2<3, false><<<Bn * Tn * 2, 256>>>(LN1, WT + WT_Q, nullptr, Q);
    k_conv2<2, false><<<Bn * Tn * 2, 256>>>(LN1, WT + WT_K, nullptr, Kb);
    k_conv2<1, false><<<Bn * Tn * 2, 256>>>(LN1, WT + WT_V, nullptr, V);

    // 5. BN stats (fold into scale/shift)
    k_bnstats<<<2 * Cn, 256>>>(Q, Kb, q_bn_g, q_bn_b, k_bn_g, k_bn_b, BN);

    // 6. attention (4-way key split)
    k_attn2<<<4 * Bn * Hh * (Pn / 128), 128>>>(Q, Kb, V, BN, PART);

    // 7. merge partials + conv_atten
    k_merge<<<(Bn * Pn * Cn) / 256, 256>>>(PART, Q, Kb, V, BN, ATT);

    // 8. proj
    k_proj<<<BPn / 8, 128>>>(ATT, WT + WT_P, proj_b, Hb);

    // 9-11. msgfa convs with residuals (on raw x)
    k_conv2<3, true><<<Bn * Tn * 2, 256>>>(XT, WT + WT_R1, XT, A1);
    k_conv2<2, true><<<Bn * Tn * 2, 256>>>(A1, WT + WT_R2, A1, A2);
    k_conv2<1, true><<<Bn * Tn * 2, 256>>>(A2, WT + WT_R3, A2, A3);

    // 12. combine: x2 = s + h, layernorm2, xm
    k_combine<<<BPn, 128>>>(A1, A2, A3, Hb, n2g, n2b, X2, LN2, XM);

    // 13. gate
    k_gate<<<(BPn + 255) / 256, 256>>>(XM, st1, st2, st3, GATE);

    // 14. final
    k_final<<<(Bn * Pn * Cn + 255) / 256, 256>>>(X2, LN2, GATE, out);
}